// round 8
// baseline (speedup 1.0000x reference)
#include <cuda_runtime.h>
#include <cuda_fp16.h>
#include <cstdint>

// x[32768,2048] fp32, bank[20,2048] fp32 -> out[32768,2048] fp32
constexpr int FEA    = 2048;
constexpr int NBANK  = 20;
constexpr int TILE_M = 32;             // 1024 tiles
constexpr int CHUNK  = 128;            // x cols per chunk
constexpr int NCH    = FEA / CHUNK;    // 16
constexpr float LAMBDA = 0.0025f;

// SMEM map (105472 B -> 2 CTAs/SM)
constexpr int SM_BANK  = 0;                       // [20 j][2048 k] fp16 swizzled
constexpr int BANKB    = NBANK * 4096;            // 81920
constexpr int SM_ZERO  = BANKB;                   // 1KB zero page (ldsm clamp)
constexpr int SM_X     = SM_ZERO + 1024;          // 82944, ring 2 x 8KB
constexpr int XSLOTB   = TILE_M * CHUNK * 2;      // 8192
constexpr int SM_LOGIT = SM_X + 2 * XSLOTB;       // 99328: [32][32] f32
constexpr int SM_ATT   = SM_LOGIT + 32 * 32 * 4;  // 103424: [32][32] fp16
constexpr int SM_TOTAL = SM_ATT + 32 * 32 * 2;    // 105472

__device__ unsigned int g_tilectr;
__global__ void reset_ctr() { g_tilectr = 0u; }

__device__ __forceinline__ uint32_t s2u(const void* p) {
    uint32_t a;
    asm("{ .reg .u64 t; cvta.to.shared.u64 t, %1; cvt.u32.u64 %0, t; }"
        : "=r"(a) : "l"(p));
    return a;
}
__device__ __forceinline__ void ldsm4(uint32_t a, uint32_t& r0, uint32_t& r1,
                                      uint32_t& r2, uint32_t& r3) {
    asm volatile("ldmatrix.sync.aligned.m8n8.x4.shared.b16 {%0,%1,%2,%3}, [%4];"
                 : "=r"(r0), "=r"(r1), "=r"(r2), "=r"(r3) : "r"(a));
}
__device__ __forceinline__ void ldsm2(uint32_t a, uint32_t& r0, uint32_t& r1) {
    asm volatile("ldmatrix.sync.aligned.m8n8.x2.shared.b16 {%0,%1}, [%2];"
                 : "=r"(r0), "=r"(r1) : "r"(a));
}
__device__ __forceinline__ void ldsm2t(uint32_t a, uint32_t& r0, uint32_t& r1) {
    asm volatile("ldmatrix.sync.aligned.m8n8.x2.trans.shared.b16 {%0,%1}, [%2];"
                 : "=r"(r0), "=r"(r1) : "r"(a));
}
__device__ __forceinline__ void mma16816(float& d0, float& d1, float& d2, float& d3,
                                         uint32_t a0, uint32_t a1, uint32_t a2, uint32_t a3,
                                         uint32_t b0, uint32_t b1) {
    asm volatile(
        "mma.sync.aligned.m16n8k16.row.col.f32.f16.f16.f32 "
        "{%0,%1,%2,%3}, {%4,%5,%6,%7}, {%8,%9}, {%0,%1,%2,%3};"
        : "+f"(d0), "+f"(d1), "+f"(d2), "+f"(d3)
        : "r"(a0), "r"(a1), "r"(a2), "r"(a3), "r"(b0), "r"(b1));
}
__device__ __forceinline__ float tanh_fast(float v) {
    float r;
    asm("tanh.approx.f32 %0, %1;" : "=f"(r) : "f"(v));
    return r;
}
__device__ __forceinline__ uint32_t h2bits(__half2 h) {
    return *reinterpret_cast<uint32_t*>(&h);
}

extern __shared__ char smc[];

__global__ void __launch_bounds__(256, 2)
memunit_hmma2(const float* __restrict__ x,
              const float* __restrict__ bank,
              float* __restrict__ out,
              int n_tiles)
{
    const uint32_t sbase = s2u(smc);
    const int tid  = threadIdx.x;
    const int warp = tid >> 5;
    const int lane = tid & 31;

    // ---- bank -> fp16 [20 j][2048 k], swizzle byte = j*4096 + (2k ^ ((j&7)<<4))
    for (int idx = tid; idx < NBANK * FEA; idx += 256) {
        const int j = idx >> 11, k = idx & (FEA - 1);
        *reinterpret_cast<__half*>(smc + SM_BANK + j * 4096 + ((2 * k) ^ ((j & 7) << 4)))
            = __float2half(bank[idx]);
    }
    for (int i = tid; i < 1024 / 4; i += 256)          // zero page
        reinterpret_cast<uint32_t*>(smc + SM_ZERO)[i] = 0u;

    const int mh = warp >> 2;              // m-half: rows mh*16..+15
    const int nt = warp & 3;               // n-tile / n-quarter

    // A frags (row-major x4)
    const int arow = mh * 16 + (lane & 7) + ((lane & 8) ? 8 : 0);
    const int akb  = (lane & 16) ? 16 : 0;
    const int asw  = (arow & 7) << 4;
    // GEMM1 B (non-trans x2), rows j = nt*8 + (lane&7); clamp rows >= 20
    const int brow = nt * 8 + (lane & 7);
    const int bkb  = (lane & 8) ? 16 : 0;
    const int bsw  = (brow & 7) << 4;
    const bool bvalid = brow < NBANK;
    const uint32_t bb = sbase + SM_BANK + brow * 4096;
    const uint32_t zp = sbase + SM_ZERO + (lane & 7) * 16;   // spread zero reads
    // GEMM2 B (trans x2), k-rows jrow0 / jrow0+16; clamp row1 >= 20
    const int jrow0 = (lane & 7) + ((lane & 8) ? 8 : 0);
    const int sw2   = (jrow0 & 7) << 4;
    const bool v1   = (jrow0 + 16) < NBANK;
    const uint32_t bt0 = sbase + SM_BANK + jrow0 * 4096;
    const uint32_t bt1 = sbase + SM_BANK + (jrow0 + 16) * 4096;
    // D / logit / out rows
    const int lr  = mh * 16 + (lane >> 2);
    const int lc2 = (lane & 3) * 2;

    __shared__ int s_tile;
    float4 pf[4];   // x prefetch: 16 f32/thread (one 32x128 chunk)

    auto ldx = [&](int tile, int c) {
        const float4* p = reinterpret_cast<const float4*>(x)
                        + (long)tile * TILE_M * (FEA / 4) + c * (CHUNK / 4);
        #pragma unroll
        for (int i = 0; i < 4; i++) {
            const int f = i * 256 + tid;          // float4 idx within chunk
            pf[i] = p[(f >> 5) * (FEA / 4) + (f & 31)];
        }
    };
    auto stx = [&](int slot) {
        char* s = smc + SM_X + slot * XSLOTB;
        #pragma unroll
        for (int i = 0; i < 4; i++) {
            const int f = i * 256 + tid;
            const int row = f >> 5, kb = (f & 31) * 8;
            uint2 pkt;
            pkt.x = h2bits(__floats2half2_rn(pf[i].x, pf[i].y));
            pkt.y = h2bits(__floats2half2_rn(pf[i].z, pf[i].w));
            *reinterpret_cast<uint2*>(s + row * 256 + (kb ^ ((row & 7) << 4))) = pkt;
        }
    };

    for (;;) {
        if (tid == 0) s_tile = (int)atomicAdd(&g_tilectr, 1u);
        __syncthreads();                       // broadcast + guards smem reuse
        const int tile = s_tile;
        if (tile >= n_tiles) break;
        const long row0 = (long)tile * TILE_M;

        // ============ GEMM1: logits[32 x 32] ================================
        ldx(tile, 0);
        float d0 = 0.f, d1 = 0.f, d2 = 0.f, d3 = 0.f;
        #pragma unroll 1
        for (int c = 0; c < NCH; c++) {
            stx(c & 1);
            if (c + 1 < NCH) ldx(tile, c + 1);
            __syncthreads();                   // slot (c&1) ready; prev reads done

            const uint32_t xs = sbase + SM_X + (c & 1) * XSLOTB + arow * 256;
            #pragma unroll
            for (int ks = 0; ks < 8; ks++) {
                uint32_t a0, a1, a2, a3, b0, b1;
                ldsm4(xs + ((ks * 32 + akb) ^ asw), a0, a1, a2, a3);
                const uint32_t ba =
                    bvalid ? bb + ((c * 256 + ks * 32 + bkb) ^ bsw) : zp;
                ldsm2(ba, b0, b1);
                mma16816(d0, d1, d2, d3, a0, a1, a2, a3, b0, b1);
            }
        }

        float* lg = reinterpret_cast<float*>(smc + SM_LOGIT);
        *reinterpret_cast<float2*>(&lg[lr * 32 + nt * 8 + lc2])       = make_float2(d0, d1);
        *reinterpret_cast<float2*>(&lg[(lr + 8) * 32 + nt * 8 + lc2]) = make_float2(d2, d3);
        __syncthreads();

        // ============ softmax -> softshrink -> softmax (1 thr/row) ==========
        if (tid < 32) {
            float att[NBANK];
            #pragma unroll
            for (int j = 0; j < NBANK; j++) att[j] = lg[tid * 32 + j];

            float m = att[0];
            #pragma unroll
            for (int j = 1; j < NBANK; j++) m = fmaxf(m, att[j]);
            float s = 0.f;
            #pragma unroll
            for (int j = 0; j < NBANK; j++) { float e = __expf(att[j] - m); att[j] = e; s += e; }
            const float inv = 1.0f / s;

            float m2 = 0.f;   // att >= 0 => softshrink = max(att - lambda, 0)
            #pragma unroll
            for (int j = 0; j < NBANK; j++) {
                float a = fmaxf(att[j] * inv - LAMBDA, 0.f);
                att[j] = a;
                m2 = fmaxf(m2, a);
            }
            float s2 = 0.f;
            #pragma unroll
            for (int j = 0; j < NBANK; j++) { float e = __expf(att[j] - m2); att[j] = e; s2 += e; }
            const float inv2 = 1.0f / s2;

            __half2* av = reinterpret_cast<__half2*>(smc + SM_ATT + tid * 64);
            #pragma unroll
            for (int jp = 0; jp < 10; jp++)
                av[jp] = __floats2half2_rn(att[2 * jp] * inv2, att[2 * jp + 1] * inv2);
            #pragma unroll
            for (int jp = 10; jp < 16; jp++)
                av[jp] = __floats2half2_rn(0.f, 0.f);
        }
        __syncthreads();

        // ============ GEMM2 + tanh: out[32 x 2048] ==========================
        uint32_t aA0[4], aA1[4];
        {
            const uint32_t ab = sbase + SM_ATT + arow * 64 + ((lane & 16) ? 16 : 0);
            ldsm4(ab,      aA0[0], aA0[1], aA0[2], aA0[3]);   // k = j 0..15
            ldsm4(ab + 32, aA1[0], aA1[1], aA1[2], aA1[3]);   // k = j 16..31
        }
        float* orow0 = out + (row0 + lr) * FEA + lc2;
        float* orow1 = out + (row0 + lr + 8) * FEA + lc2;

        #pragma unroll 4
        for (int t2 = 0; t2 < 64; t2++) {
            const int nb = (nt * 64 + t2) * 8;
            const int nbyte = (nb * 2) ^ sw2;
            uint32_t b00, b01, b10, b11;
            ldsm2t(bt0 + nbyte, b00, b01);
            ldsm2t(v1 ? bt1 + nbyte : zp, b10, b11);
            float e0 = 0.f, e1 = 0.f, e2 = 0.f, e3 = 0.f;
            mma16816(e0, e1, e2, e3, aA0[0], aA0[1], aA0[2], aA0[3], b00, b01);
            mma16816(e0, e1, e2, e3, aA1[0], aA1[1], aA1[2], aA1[3], b10, b11);
            *reinterpret_cast<float2*>(orow0 + nb) =
                make_float2(tanh_fast(e0), tanh_fast(e1));
            *reinterpret_cast<float2*>(orow1 + nb) =
                make_float2(tanh_fast(e2), tanh_fast(e3));
        }
        // next-tile top __syncthreads guards logits/att/x-ring reuse
    }
}

extern "C" void kernel_launch(void* const* d_in, const int* in_sizes, int n_in,
                              void* d_out, int out_size)
{
    const float* x    = reinterpret_cast<const float*>(d_in[0]);
    const float* bank = reinterpret_cast<const float*>(d_in[1]);
    float* out        = reinterpret_cast<float*>(d_out);

    const int rows    = in_sizes[0] / FEA;   // 32768
    const int n_tiles = rows / TILE_M;       // 1024

    cudaFuncSetAttribute(memunit_hmma2,
                         cudaFuncAttributeMaxDynamicSharedMemorySize, SM_TOTAL);

    int dev = 0, sms = 148;
    cudaGetDevice(&dev);
    cudaDeviceGetAttribute(&sms, cudaDevAttrMultiProcessorCount, dev);

    int grid = 2 * sms;
    if (grid > n_tiles) grid = n_tiles;

    reset_ctr<<<1, 1>>>();
    memunit_hmma2<<<grid, 256, SM_TOTAL>>>(x, bank, out, n_tiles);
}